// round 16
// baseline (speedup 1.0000x reference)
#include <cuda_runtime.h>
#include <cuda_bf16.h>
#include <cuda_fp16.h>
#include <cstdint>

#define N_NODES 100000
#define N_EDGES 25000
#define N_INC   600000
#define D       128
#define ATTR_VEC4 (25000*32/4)
#define E_SPLIT 12544           // 98 * 128, tile-aligned edge split

typedef unsigned long long ull;

// ---------------- scratch ----------------
__device__ __half g_xh[N_NODES*D];    // fp16 copy of input x
__device__ __half g_hh[N_NODES*D];    // node features between layers (fp16)
__device__ float  g_es [N_EDGES*D];   // edge aggregate (fp32)
__device__ __half g_ef2h[N_EDGES*D];  // edge aggregate @ W (fp16 storage)
__device__ __nv_bfloat16 g_wh[3*16384];   // W hi planes (3 layers)
__device__ __nv_bfloat16 g_wl[3*16384];   // W lo planes
__device__ int   g_cnt_e[N_EDGES];
__device__ int   g_cnt_n[N_NODES];
__device__ int   g_off_e[N_EDGES];
__device__ int   g_end_e[N_EDGES];
__device__ int   g_off_n[N_NODES];
__device__ int   g_end_n[N_NODES];
__device__ int   g_cur_e[N_EDGES];
__device__ int   g_cur_n[N_NODES];
__device__ int   g_csr_e[N_INC];
__device__ int   g_csr_n[N_INC];
__device__ float g_binv[N_EDGES];
__device__ float g_dinv[N_NODES];
__device__ int   g_cursors[2];

// ---------------- helpers ----------------
__device__ __forceinline__ uint32_t smem_u32(const void* p) {
    uint32_t a;
    asm("{ .reg .u64 t; cvta.to.shared.u64 t, %1; cvt.u32.u64 %0, t; }"
        : "=r"(a) : "l"(p));
    return a;
}
__device__ __forceinline__ void ldsm4(uint32_t* r, uint32_t addr) {
    asm volatile("ldmatrix.sync.aligned.m8n8.x4.shared.b16 {%0,%1,%2,%3}, [%4];"
                 : "=r"(r[0]), "=r"(r[1]), "=r"(r[2]), "=r"(r[3]) : "r"(addr));
}
__device__ __forceinline__ void ldsm2t(uint32_t* r, uint32_t addr) {
    asm volatile("ldmatrix.sync.aligned.m8n8.x2.trans.shared.b16 {%0,%1}, [%2];"
                 : "=r"(r[0]), "=r"(r[1]) : "r"(addr));
}
__device__ __forceinline__ void mma16816(float* c, const uint32_t* a,
                                         const uint32_t* b) {
    asm volatile(
        "mma.sync.aligned.m16n8k16.row.col.f32.bf16.bf16.f32 "
        "{%0,%1,%2,%3}, {%4,%5,%6,%7}, {%8,%9}, {%0,%1,%2,%3};"
        : "+f"(c[0]), "+f"(c[1]), "+f"(c[2]), "+f"(c[3])
        : "r"(a[0]), "r"(a[1]), "r"(a[2]), "r"(a[3]), "r"(b[0]), "r"(b[1]));
}

// ---------------- CSR build (fused both sides; counters zero on entry) -----
__global__ void k_count(const int* __restrict__ ni, const int* __restrict__ ei) {
    int i = blockIdx.x * blockDim.x + threadIdx.x;
    if (i < N_INC) {
        atomicAdd(&g_cnt_e[ei[i]], 1);
        atomicAdd(&g_cnt_n[ni[i]], 1);
    }
}

__global__ void k_assign() {
    int i = blockIdx.x * blockDim.x + threadIdx.x;
    int lane = threadIdx.x & 31;
    // edges
    {
        int c = (i < N_EDGES) ? g_cnt_e[i] : 0;
        int pre = c;
        #pragma unroll
        for (int o = 1; o < 32; o <<= 1) {
            int n = __shfl_up_sync(0xffffffffu, pre, o);
            if (lane >= o) pre += n;
        }
        int total = __shfl_sync(0xffffffffu, pre, 31);
        int base = 0;
        if (lane == 31 && total > 0) base = atomicAdd(&g_cursors[0], total);
        base = __shfl_sync(0xffffffffu, base, 31);
        if (i < N_EDGES) {
            int o = base + pre - c;
            g_off_e[i] = o;
            g_end_e[i] = o + c;
            g_binv[i]  = (c > 0) ? (1.0f / (float)c) : 0.0f;
        }
    }
    // nodes
    {
        int c = (i < N_NODES) ? g_cnt_n[i] : 0;
        int pre = c;
        #pragma unroll
        for (int o = 1; o < 32; o <<= 1) {
            int n = __shfl_up_sync(0xffffffffu, pre, o);
            if (lane >= o) pre += n;
        }
        int total = __shfl_sync(0xffffffffu, pre, 31);
        int base = 0;
        if (lane == 31 && total > 0) base = atomicAdd(&g_cursors[1], total);
        base = __shfl_sync(0xffffffffu, base, 31);
        if (i < N_NODES) {
            int o = base + pre - c;
            g_off_n[i] = o;
            g_end_n[i] = o + c;
            g_dinv[i]  = (c > 0) ? (1.0f / (float)c) : 0.0f;
        }
    }
}

__global__ void k_fill(const int* __restrict__ ni, const int* __restrict__ ei) {
    int i = blockIdx.x * blockDim.x + threadIdx.x;
    if (i < N_INC) {
        int e = ei[i], n = ni[i];
        int pe = atomicAdd(&g_cur_e[e], 1);
        g_csr_e[g_off_e[e] + pe] = n;
        int pn = atomicAdd(&g_cur_n[n], 1);
        g_csr_n[g_off_n[n] + pn] = e;
    }
}

// ---------------- x -> fp16 conversion (16B/thread) ----------------
__global__ void k_xconv(const float* __restrict__ x) {
    int i = blockIdx.x * blockDim.x + threadIdx.x;   // 8-float group
    if (i < N_NODES * D / 8) {
        const float4* xp = (const float4*)x + 2 * (size_t)i;
        float4 a = xp[0], b = xp[1];
        uint4 o;
        *reinterpret_cast<__half2*>(&o.x) = __floats2half2_rn(a.x, a.y);
        *reinterpret_cast<__half2*>(&o.y) = __floats2half2_rn(a.z, a.w);
        *reinterpret_cast<__half2*>(&o.z) = __floats2half2_rn(b.x, b.y);
        *reinterpret_cast<__half2*>(&o.w) = __floats2half2_rn(b.z, b.w);
        ((uint4*)g_xh)[i] = o;
    }
}

// ---------------- W bf16-split prep ----------------
__global__ void k_wsplit(const float* __restrict__ W1,
                         const float* __restrict__ W2,
                         const float* __restrict__ W3) {
    int i = blockIdx.x * blockDim.x + threadIdx.x;
    if (i >= 3 * 16384) return;
    int l = i >> 14, j = i & 16383;
    const float* W = (l == 0) ? W1 : (l == 1) ? W2 : W3;
    float w = W[j];
    __nv_bfloat16 h = __float2bfloat16(w);
    g_wh[i] = h;
    g_wl[i] = __float2bfloat16(w - __bfloat162float(h));
}

// ---------------- GEMM via HMMA (rows [m_base, ...)), fp16 output ----------
#define A_STR 40
#define B_STR 136

__global__ void __launch_bounds__(256, 2)
k_gemm_mma(const float* __restrict__ A, int layer, int m_base, int nrows) {
    __shared__ __nv_bfloat16 sAh[128 * A_STR];
    __shared__ __nv_bfloat16 sAl[128 * A_STR];
    __shared__ __nv_bfloat16 sBh[32 * B_STR];
    __shared__ __nv_bfloat16 sBl[32 * B_STR];

    const int tid  = threadIdx.x;
    const int wid  = tid >> 5, lane = tid & 31;
    const int m0   = m_base + blockIdx.x * 128;
    const int r0   = wid * 16;

    const __nv_bfloat16* Wh = &g_wh[layer * 16384];
    const __nv_bfloat16* Wl = &g_wl[layer * 16384];

    const uint32_t ah_b = smem_u32(sAh);
    const uint32_t al_b = smem_u32(sAl);
    const uint32_t bh_b = smem_u32(sBh);
    const uint32_t bl_b = smem_u32(sBl);

    const int a_lr = (lane & 7) + ((lane & 8) ? 8 : 0);
    const int a_lc = (lane & 16) ? 8 : 0;
    const int b_lr = (lane & 7) + (((lane >> 3) & 1) ? 8 : 0);

    float acc[16][4];
    #pragma unroll
    for (int t = 0; t < 16; t++)
        #pragma unroll
        for (int j = 0; j < 4; j++) acc[t][j] = 0.f;

    const int lrow = tid >> 1, lkq = (tid & 1) * 16;
    const int lkr = tid >> 3, lnq = (tid & 7) * 16;

    for (int kc = 0; kc < 128; kc += 32) {
        {
            int grow = m0 + lrow;
            const float4* ap = (grow < nrows)
                ? (const float4*)&A[(size_t)grow * D + kc + lkq] : nullptr;
            #pragma unroll
            for (int q = 0; q < 4; q++) {
                float4 v = ap ? ap[q] : make_float4(0.f, 0.f, 0.f, 0.f);
                float f[4] = { v.x, v.y, v.z, v.w };
                #pragma unroll
                for (int u = 0; u < 2; u++) {
                    __nv_bfloat16 h0 = __float2bfloat16(f[2*u]);
                    __nv_bfloat16 h1 = __float2bfloat16(f[2*u+1]);
                    __nv_bfloat16 l0 = __float2bfloat16(f[2*u]   - __bfloat162float(h0));
                    __nv_bfloat16 l1 = __float2bfloat16(f[2*u+1] - __bfloat162float(h1));
                    int k = lkq + q * 4 + u * 2;
                    *(__nv_bfloat162*)&sAh[lrow * A_STR + k] = __nv_bfloat162(h0, h1);
                    *(__nv_bfloat162*)&sAl[lrow * A_STR + k] = __nv_bfloat162(l0, l1);
                }
            }
            size_t wo = (size_t)(kc + lkr) * D + lnq;
            uint4 wh0 = *(const uint4*)&Wh[wo];
            uint4 wh1 = *(const uint4*)&Wh[wo + 8];
            uint4 wl0 = *(const uint4*)&Wl[wo];
            uint4 wl1 = *(const uint4*)&Wl[wo + 8];
            int bo = lkr * B_STR + lnq;
            *(uint4*)&sBh[bo]     = wh0;
            *(uint4*)&sBh[bo + 8] = wh1;
            *(uint4*)&sBl[bo]     = wl0;
            *(uint4*)&sBl[bo + 8] = wl1;
        }
        __syncthreads();

        #pragma unroll
        for (int ks = 0; ks < 32; ks += 16) {
            uint32_t ah[4], al[4];
            uint32_t aoff = (uint32_t)((r0 + a_lr) * A_STR + ks + a_lc) * 2;
            ldsm4(ah, ah_b + aoff);
            ldsm4(al, al_b + aoff);
            #pragma unroll
            for (int nt = 0; nt < 16; nt++) {
                uint32_t bh[2], bl[2];
                uint32_t boff = (uint32_t)((ks + b_lr) * B_STR + nt * 8) * 2;
                ldsm2t(bh, bh_b + boff);
                ldsm2t(bl, bl_b + boff);
                mma16816(acc[nt], ah, bh);
                mma16816(acc[nt], al, bh);
                mma16816(acc[nt], ah, bl);
            }
        }
        __syncthreads();
    }

    // epilogue: convert fp32 acc -> fp16 storage
    const int grp = lane >> 2, tig = lane & 3;
    int row0 = m0 + r0 + grp;
    int row1 = row0 + 8;
    #pragma unroll
    for (int nt = 0; nt < 16; nt++) {
        int col = nt * 8 + tig * 2;
        if (row0 < nrows)
            *(__half2*)&g_ef2h[(size_t)row0 * D + col] =
                __floats2half2_rn(acc[nt][0], acc[nt][1]);
        if (row1 < nrows)
            *(__half2*)&g_ef2h[(size_t)row1 * D + col] =
                __floats2half2_rn(acc[nt][2], acc[nt][3]);
    }
}

// ---------------- nodes -> hyperedges gather (fp16 src, edge range) --------
__global__ void k_edge_gather(const __half* __restrict__ in, int e_begin, int e_end) {
    int w = e_begin + ((blockIdx.x * blockDim.x + threadIdx.x) >> 5);
    int lane = threadIdx.x & 31;
    if (w >= e_end) return;
    int s = g_off_e[w], t = g_end_e[w];
    float4 acc = make_float4(0.f, 0.f, 0.f, 0.f);
    #pragma unroll 8
    for (int j = s; j < t; j++) {
        int nn = __ldg(&g_csr_e[j]);
        uint2 u = *(const uint2*)&in[(size_t)nn * D + lane * 4];
        __half2 h0 = *reinterpret_cast<__half2*>(&u.x);
        __half2 h1 = *reinterpret_cast<__half2*>(&u.y);
        float2 f0 = __half22float2(h0);
        float2 f1 = __half22float2(h1);
        acc.x += f0.x; acc.y += f0.y; acc.z += f1.x; acc.w += f1.y;
    }
    float bi = g_binv[w];
    acc.x *= bi; acc.y *= bi; acc.z *= bi; acc.w *= bi;
    *(float4*)&g_es[(size_t)w * D + lane * 4] = acc;
}

// ---------------- hyperedges -> nodes gather (fp16 src) + bias (+relu) -----
__global__ void k_node_gather(float* __restrict__ outf, __half* __restrict__ outh,
                              const float* __restrict__ b, int doRelu) {
    int w = (blockIdx.x * blockDim.x + threadIdx.x) >> 5;
    int lane = threadIdx.x & 31;
    if (w >= N_NODES) return;
    int s = g_off_n[w], t = g_end_n[w];
    float4 acc = make_float4(0.f, 0.f, 0.f, 0.f);
    #pragma unroll 8
    for (int j = s; j < t; j++) {
        int ee = __ldg(&g_csr_n[j]);
        uint2 u = *(const uint2*)&g_ef2h[(size_t)ee * D + lane * 4];
        __half2 h0 = *reinterpret_cast<__half2*>(&u.x);
        __half2 h1 = *reinterpret_cast<__half2*>(&u.y);
        float2 f0 = __half22float2(h0);
        float2 f1 = __half22float2(h1);
        acc.x += f0.x; acc.y += f0.y; acc.z += f1.x; acc.w += f1.y;
    }
    float di = g_dinv[w];
    float4 bv = ((const float4*)b)[lane];
    float4 r;
    r.x = acc.x * di + bv.x;
    r.y = acc.y * di + bv.y;
    r.z = acc.z * di + bv.z;
    r.w = acc.w * di + bv.w;
    if (doRelu) {
        r.x = fmaxf(r.x, 0.f); r.y = fmaxf(r.y, 0.f);
        r.z = fmaxf(r.z, 0.f); r.w = fmaxf(r.w, 0.f);
    }
    if (outh) {
        uint2 u;
        *reinterpret_cast<__half2*>(&u.x) = __floats2half2_rn(r.x, r.y);
        *reinterpret_cast<__half2*>(&u.y) = __floats2half2_rn(r.z, r.w);
        *(uint2*)&outh[(size_t)w * D + lane * 4] = u;
    } else {
        *(float4*)&outf[(size_t)w * D + lane * 4] = r;
    }
}

// ---------------- attr passthrough / counter cleanup ----------------
__global__ void k_copy_attr(const float4* __restrict__ in, float4* __restrict__ out) {
    int i = blockIdx.x * blockDim.x + threadIdx.x;
    if (i < ATTR_VEC4) out[i] = in[i];
}
__global__ void k_cleanup() {
    int i = blockIdx.x * blockDim.x + threadIdx.x;
    if (i < N_EDGES) { g_cnt_e[i] = 0; g_cur_e[i] = 0; }
    if (i < N_NODES) { g_cnt_n[i] = 0; g_cur_n[i] = 0; }
    if (i < 2) g_cursors[i] = 0;
}

// ---------------- launch ----------------
extern "C" void kernel_launch(void* const* d_in, const int* in_sizes, int n_in,
                              void* d_out, int out_size) {
    const float* x        = (const float*)d_in[0];
    const int*   node_idx = (const int*)  d_in[1];
    const int*   edge_idx = (const int*)  d_in[2];
    const float* attr     = (const float*)d_in[3];
    const float* W1 = (const float*)d_in[4];
    const float* b1 = (const float*)d_in[5];
    const float* W2 = (const float*)d_in[6];
    const float* b2 = (const float*)d_in[7];
    const float* W3 = (const float*)d_in[8];
    const float* b3 = (const float*)d_in[9];
    float* out = (float*)d_out;

    static cudaStream_t s1 = nullptr, s2 = nullptr;
    static cudaEvent_t  e0, e_csr, e_ws, e_xc, e_j;
    static cudaEvent_t  e_g1[3], e_h[3];
    if (!s1) {
        cudaStreamCreateWithFlags(&s1, cudaStreamNonBlocking);
        cudaStreamCreateWithFlags(&s2, cudaStreamNonBlocking);
        cudaEventCreateWithFlags(&e0,   cudaEventDisableTiming);
        cudaEventCreateWithFlags(&e_csr,cudaEventDisableTiming);
        cudaEventCreateWithFlags(&e_ws, cudaEventDisableTiming);
        cudaEventCreateWithFlags(&e_xc, cudaEventDisableTiming);
        cudaEventCreateWithFlags(&e_j,  cudaEventDisableTiming);
        for (int i = 0; i < 3; i++) {
            cudaEventCreateWithFlags(&e_g1[i], cudaEventDisableTiming);
            cudaEventCreateWithFlags(&e_h[i],  cudaEventDisableTiming);
        }
    }

    float* p_es;
    __half *p_xh, *p_hh;
    cudaGetSymbolAddress((void**)&p_es, g_es);
    cudaGetSymbolAddress((void**)&p_xh, g_xh);
    cudaGetSymbolAddress((void**)&p_hh, g_hh);

    const int half_tiles = E_SPLIT / 128;                       // 98
    const int eg0_grid   = (E_SPLIT * 32) / 256;                // 1568
    const int eg1_grid   = ((N_EDGES - E_SPLIT) * 32 + 255) / 256;
    const int ng_grid    = (N_NODES * 32 + 255) / 256;          // 12500
    const int inc_grid   = (N_INC + 255) / 256;

    cudaEventRecord(e0, 0);

    // s2: xconv immediately (only needs x)
    cudaStreamWaitEvent(s2, e0, 0);
    k_xconv<<<(N_NODES * D / 8 + 255) / 256, 256, 0, s2>>>(x);
    cudaEventRecord(e_xc, s2);

    // s1: wsplit, attr, (cleanup after CSR)
    cudaStreamWaitEvent(s1, e0, 0);
    k_wsplit<<<(3 * 16384 + 255) / 256, 256, 0, s1>>>(W1, W2, W3);
    cudaEventRecord(e_ws, s1);
    k_copy_attr<<<(ATTR_VEC4 + 255) / 256, 256, 0, s1>>>(
        (const float4*)attr, (float4*)(out + (size_t)N_NODES * D));

    // s0: fused CSR build (both sides)
    k_count <<<inc_grid, 256>>>(node_idx, edge_idx);
    k_assign<<<(N_NODES + 255) / 256, 256>>>();
    k_fill  <<<inc_grid, 256>>>(node_idx, edge_idx);
    cudaEventRecord(e_csr, 0);

    cudaStreamWaitEvent(s1, e_csr, 0);
    k_cleanup<<<(N_NODES + 255) / 256, 256, 0, s1>>>();
    cudaEventRecord(e_j, s1);

    // layers: s0 does half0 + ng; s2 does half1
    const __half* layer_in[3] = { p_xh, p_hh, p_hh };
    for (int l = 0; l < 3; l++) {
        const float* bb = (l == 0) ? b1 : (l == 1) ? b2 : b3;
        // s2: second half (xconv already on s2; wait CSR / prev layer)
        cudaStreamWaitEvent(s2, (l == 0) ? e_csr : e_h[l - 1], 0);
        k_edge_gather<<<eg1_grid, 256, 0, s2>>>(layer_in[l], E_SPLIT, N_EDGES);
        if (l == 0) cudaStreamWaitEvent(s2, e_ws, 0);
        k_gemm_mma<<<half_tiles, 256, 0, s2>>>(p_es, l, E_SPLIT, N_EDGES);
        cudaEventRecord(e_g1[l], s2);

        // s0: first half (CSR is same-stream; need xconv for layer 0)
        if (l == 0) cudaStreamWaitEvent(0, e_xc, 0);
        k_edge_gather<<<eg0_grid, 256>>>(layer_in[l], 0, E_SPLIT);
        if (l == 0) cudaStreamWaitEvent(0, e_ws, 0);
        k_gemm_mma<<<half_tiles, 256>>>(p_es, l, 0, N_EDGES);
        cudaStreamWaitEvent(0, e_g1[l], 0);
        if (l < 2) k_node_gather<<<ng_grid, 256>>>(nullptr, p_hh, bb, 1);
        else       k_node_gather<<<ng_grid, 256>>>(out, nullptr, bb, 0);
        cudaEventRecord(e_h[l], 0);
    }

    cudaStreamWaitEvent(0, e_j, 0);
}

// round 17
// speedup vs baseline: 1.0328x; 1.0328x over previous
#include <cuda_runtime.h>
#include <cuda_bf16.h>
#include <cuda_fp16.h>
#include <cstdint>

#define N_NODES 100000
#define N_EDGES 25000
#define N_INC   600000
#define D       128
#define ATTR_VEC4 (25000*32/4)
#define E_SPLIT 12544           // 98 * 128, tile-aligned edge split

typedef unsigned long long ull;

// ---------------- scratch ----------------
__device__ __half g_xh[N_NODES*D];    // fp16 copy of input x
__device__ __half g_hh[N_NODES*D];    // node features between layers (fp16)
__device__ float  g_es [N_EDGES*D];   // edge aggregate (fp32)
__device__ __half g_ef2h[N_EDGES*D];  // edge aggregate @ W (fp16 storage)
__device__ __nv_bfloat16 g_wh[3*16384];   // W hi planes (3 layers)
__device__ __nv_bfloat16 g_wl[3*16384];   // W lo planes
__device__ int   g_cnt_e[N_EDGES];
__device__ int   g_cnt_n[N_NODES];
__device__ int   g_off_e[N_EDGES];
__device__ int   g_end_e[N_EDGES];
__device__ int   g_off_n[N_NODES];
__device__ int   g_end_n[N_NODES];
__device__ int   g_cur_e[N_EDGES];
__device__ int   g_cur_n[N_NODES];
__device__ int   g_csr_e[N_INC];
__device__ int   g_csr_n[N_INC];
__device__ float g_binv[N_EDGES];
__device__ float g_dinv[N_NODES];
__device__ int   g_cursors[2];

// ---------------- helpers ----------------
__device__ __forceinline__ uint32_t smem_u32(const void* p) {
    uint32_t a;
    asm("{ .reg .u64 t; cvta.to.shared.u64 t, %1; cvt.u32.u64 %0, t; }"
        : "=r"(a) : "l"(p));
    return a;
}
__device__ __forceinline__ void ldsm4(uint32_t* r, uint32_t addr) {
    asm volatile("ldmatrix.sync.aligned.m8n8.x4.shared.b16 {%0,%1,%2,%3}, [%4];"
                 : "=r"(r[0]), "=r"(r[1]), "=r"(r[2]), "=r"(r[3]) : "r"(addr));
}
__device__ __forceinline__ void ldsm2t(uint32_t* r, uint32_t addr) {
    asm volatile("ldmatrix.sync.aligned.m8n8.x2.trans.shared.b16 {%0,%1}, [%2];"
                 : "=r"(r[0]), "=r"(r[1]) : "r"(addr));
}
__device__ __forceinline__ void mma16816(float* c, const uint32_t* a,
                                         const uint32_t* b) {
    asm volatile(
        "mma.sync.aligned.m16n8k16.row.col.f32.bf16.bf16.f32 "
        "{%0,%1,%2,%3}, {%4,%5,%6,%7}, {%8,%9}, {%0,%1,%2,%3};"
        : "+f"(c[0]), "+f"(c[1]), "+f"(c[2]), "+f"(c[3])
        : "r"(a[0]), "r"(a[1]), "r"(a[2]), "r"(a[3]), "r"(b[0]), "r"(b[1]));
}

// ---------------- CSR build, split edge/node sides ----------------
__global__ void k_count_e(const int* __restrict__ ei) {
    int i = blockIdx.x * blockDim.x + threadIdx.x;
    if (i < N_INC) atomicAdd(&g_cnt_e[ei[i]], 1);
}
__global__ void k_count_n(const int* __restrict__ ni) {
    int i = blockIdx.x * blockDim.x + threadIdx.x;
    if (i < N_INC) atomicAdd(&g_cnt_n[ni[i]], 1);
}
__global__ void k_assign_e() {
    int i = blockIdx.x * blockDim.x + threadIdx.x;
    int lane = threadIdx.x & 31;
    int c = (i < N_EDGES) ? g_cnt_e[i] : 0;
    int pre = c;
    #pragma unroll
    for (int o = 1; o < 32; o <<= 1) {
        int n = __shfl_up_sync(0xffffffffu, pre, o);
        if (lane >= o) pre += n;
    }
    int total = __shfl_sync(0xffffffffu, pre, 31);
    int base = 0;
    if (lane == 31 && total > 0) base = atomicAdd(&g_cursors[0], total);
    base = __shfl_sync(0xffffffffu, base, 31);
    if (i < N_EDGES) {
        int o = base + pre - c;
        g_off_e[i] = o;
        g_end_e[i] = o + c;
        g_binv[i]  = (c > 0) ? (1.0f / (float)c) : 0.0f;
    }
}
__global__ void k_assign_n() {
    int i = blockIdx.x * blockDim.x + threadIdx.x;
    int lane = threadIdx.x & 31;
    int c = (i < N_NODES) ? g_cnt_n[i] : 0;
    int pre = c;
    #pragma unroll
    for (int o = 1; o < 32; o <<= 1) {
        int n = __shfl_up_sync(0xffffffffu, pre, o);
        if (lane >= o) pre += n;
    }
    int total = __shfl_sync(0xffffffffu, pre, 31);
    int base = 0;
    if (lane == 31 && total > 0) base = atomicAdd(&g_cursors[1], total);
    base = __shfl_sync(0xffffffffu, base, 31);
    if (i < N_NODES) {
        int o = base + pre - c;
        g_off_n[i] = o;
        g_end_n[i] = o + c;
        g_dinv[i]  = (c > 0) ? (1.0f / (float)c) : 0.0f;
    }
}
__global__ void k_fill_e(const int* __restrict__ ni, const int* __restrict__ ei) {
    int i = blockIdx.x * blockDim.x + threadIdx.x;
    if (i < N_INC) {
        int e = ei[i];
        int pe = atomicAdd(&g_cur_e[e], 1);
        g_csr_e[g_off_e[e] + pe] = ni[i];
    }
}
__global__ void k_fill_n(const int* __restrict__ ni, const int* __restrict__ ei) {
    int i = blockIdx.x * blockDim.x + threadIdx.x;
    if (i < N_INC) {
        int n = ni[i];
        int pn = atomicAdd(&g_cur_n[n], 1);
        g_csr_n[g_off_n[n] + pn] = ei[i];
    }
}

// ---------------- x -> fp16 conversion (16B/thread) ----------------
__global__ void k_xconv(const float* __restrict__ x) {
    int i = blockIdx.x * blockDim.x + threadIdx.x;   // 8-float group
    if (i < N_NODES * D / 8) {
        const float4* xp = (const float4*)x + 2 * (size_t)i;
        float4 a = xp[0], b = xp[1];
        uint4 o;
        *reinterpret_cast<__half2*>(&o.x) = __floats2half2_rn(a.x, a.y);
        *reinterpret_cast<__half2*>(&o.y) = __floats2half2_rn(a.z, a.w);
        *reinterpret_cast<__half2*>(&o.z) = __floats2half2_rn(b.x, b.y);
        *reinterpret_cast<__half2*>(&o.w) = __floats2half2_rn(b.z, b.w);
        ((uint4*)g_xh)[i] = o;
    }
}

// ---------------- W bf16-split prep ----------------
__global__ void k_wsplit(const float* __restrict__ W1,
                         const float* __restrict__ W2,
                         const float* __restrict__ W3) {
    int i = blockIdx.x * blockDim.x + threadIdx.x;
    if (i >= 3 * 16384) return;
    int l = i >> 14, j = i & 16383;
    const float* W = (l == 0) ? W1 : (l == 1) ? W2 : W3;
    float w = W[j];
    __nv_bfloat16 h = __float2bfloat16(w);
    g_wh[i] = h;
    g_wl[i] = __float2bfloat16(w - __bfloat162float(h));
}

// ---------------- GEMM via HMMA (rows [m_base, ...)), fp16 output ----------
#define A_STR 40
#define B_STR 136

__global__ void __launch_bounds__(256, 2)
k_gemm_mma(const float* __restrict__ A, int layer, int m_base, int nrows) {
    __shared__ __nv_bfloat16 sAh[128 * A_STR];
    __shared__ __nv_bfloat16 sAl[128 * A_STR];
    __shared__ __nv_bfloat16 sBh[32 * B_STR];
    __shared__ __nv_bfloat16 sBl[32 * B_STR];

    const int tid  = threadIdx.x;
    const int wid  = tid >> 5, lane = tid & 31;
    const int m0   = m_base + blockIdx.x * 128;
    const int r0   = wid * 16;

    const __nv_bfloat16* Wh = &g_wh[layer * 16384];
    const __nv_bfloat16* Wl = &g_wl[layer * 16384];

    const uint32_t ah_b = smem_u32(sAh);
    const uint32_t al_b = smem_u32(sAl);
    const uint32_t bh_b = smem_u32(sBh);
    const uint32_t bl_b = smem_u32(sBl);

    const int a_lr = (lane & 7) + ((lane & 8) ? 8 : 0);
    const int a_lc = (lane & 16) ? 8 : 0;
    const int b_lr = (lane & 7) + (((lane >> 3) & 1) ? 8 : 0);

    float acc[16][4];
    #pragma unroll
    for (int t = 0; t < 16; t++)
        #pragma unroll
        for (int j = 0; j < 4; j++) acc[t][j] = 0.f;

    const int lrow = tid >> 1, lkq = (tid & 1) * 16;
    const int lkr = tid >> 3, lnq = (tid & 7) * 16;

    for (int kc = 0; kc < 128; kc += 32) {
        {
            int grow = m0 + lrow;
            const float4* ap = (grow < nrows)
                ? (const float4*)&A[(size_t)grow * D + kc + lkq] : nullptr;
            #pragma unroll
            for (int q = 0; q < 4; q++) {
                float4 v = ap ? ap[q] : make_float4(0.f, 0.f, 0.f, 0.f);
                float f[4] = { v.x, v.y, v.z, v.w };
                #pragma unroll
                for (int u = 0; u < 2; u++) {
                    __nv_bfloat16 h0 = __float2bfloat16(f[2*u]);
                    __nv_bfloat16 h1 = __float2bfloat16(f[2*u+1]);
                    __nv_bfloat16 l0 = __float2bfloat16(f[2*u]   - __bfloat162float(h0));
                    __nv_bfloat16 l1 = __float2bfloat16(f[2*u+1] - __bfloat162float(h1));
                    int k = lkq + q * 4 + u * 2;
                    *(__nv_bfloat162*)&sAh[lrow * A_STR + k] = __nv_bfloat162(h0, h1);
                    *(__nv_bfloat162*)&sAl[lrow * A_STR + k] = __nv_bfloat162(l0, l1);
                }
            }
            size_t wo = (size_t)(kc + lkr) * D + lnq;
            uint4 wh0 = *(const uint4*)&Wh[wo];
            uint4 wh1 = *(const uint4*)&Wh[wo + 8];
            uint4 wl0 = *(const uint4*)&Wl[wo];
            uint4 wl1 = *(const uint4*)&Wl[wo + 8];
            int bo = lkr * B_STR + lnq;
            *(uint4*)&sBh[bo]     = wh0;
            *(uint4*)&sBh[bo + 8] = wh1;
            *(uint4*)&sBl[bo]     = wl0;
            *(uint4*)&sBl[bo + 8] = wl1;
        }
        __syncthreads();

        #pragma unroll
        for (int ks = 0; ks < 32; ks += 16) {
            uint32_t ah[4], al[4];
            uint32_t aoff = (uint32_t)((r0 + a_lr) * A_STR + ks + a_lc) * 2;
            ldsm4(ah, ah_b + aoff);
            ldsm4(al, al_b + aoff);
            #pragma unroll
            for (int nt = 0; nt < 16; nt++) {
                uint32_t bh[2], bl[2];
                uint32_t boff = (uint32_t)((ks + b_lr) * B_STR + nt * 8) * 2;
                ldsm2t(bh, bh_b + boff);
                ldsm2t(bl, bl_b + boff);
                mma16816(acc[nt], ah, bh);
                mma16816(acc[nt], al, bh);
                mma16816(acc[nt], ah, bl);
            }
        }
        __syncthreads();
    }

    // epilogue: convert fp32 acc -> fp16 storage
    const int grp = lane >> 2, tig = lane & 3;
    int row0 = m0 + r0 + grp;
    int row1 = row0 + 8;
    #pragma unroll
    for (int nt = 0; nt < 16; nt++) {
        int col = nt * 8 + tig * 2;
        if (row0 < nrows)
            *(__half2*)&g_ef2h[(size_t)row0 * D + col] =
                __floats2half2_rn(acc[nt][0], acc[nt][1]);
        if (row1 < nrows)
            *(__half2*)&g_ef2h[(size_t)row1 * D + col] =
                __floats2half2_rn(acc[nt][2], acc[nt][3]);
    }
}

// ---------------- nodes -> hyperedges gather (fp16 src, edge range) --------
__global__ void k_edge_gather(const __half* __restrict__ in, int e_begin, int e_end) {
    int w = e_begin + ((blockIdx.x * blockDim.x + threadIdx.x) >> 5);
    int lane = threadIdx.x & 31;
    if (w >= e_end) return;
    int s = g_off_e[w], t = g_end_e[w];
    float4 acc = make_float4(0.f, 0.f, 0.f, 0.f);
    #pragma unroll 8
    for (int j = s; j < t; j++) {
        int nn = __ldg(&g_csr_e[j]);
        uint2 u = *(const uint2*)&in[(size_t)nn * D + lane * 4];
        __half2 h0 = *reinterpret_cast<__half2*>(&u.x);
        __half2 h1 = *reinterpret_cast<__half2*>(&u.y);
        float2 f0 = __half22float2(h0);
        float2 f1 = __half22float2(h1);
        acc.x += f0.x; acc.y += f0.y; acc.z += f1.x; acc.w += f1.y;
    }
    float bi = g_binv[w];
    acc.x *= bi; acc.y *= bi; acc.z *= bi; acc.w *= bi;
    *(float4*)&g_es[(size_t)w * D + lane * 4] = acc;
}

// ---------------- hyperedges -> nodes gather (fp16 src) + bias (+relu) -----
__global__ void k_node_gather(float* __restrict__ outf, __half* __restrict__ outh,
                              const float* __restrict__ b, int doRelu) {
    int w = (blockIdx.x * blockDim.x + threadIdx.x) >> 5;
    int lane = threadIdx.x & 31;
    if (w >= N_NODES) return;
    int s = g_off_n[w], t = g_end_n[w];
    float4 acc = make_float4(0.f, 0.f, 0.f, 0.f);
    #pragma unroll 8
    for (int j = s; j < t; j++) {
        int ee = __ldg(&g_csr_n[j]);
        uint2 u = *(const uint2*)&g_ef2h[(size_t)ee * D + lane * 4];
        __half2 h0 = *reinterpret_cast<__half2*>(&u.x);
        __half2 h1 = *reinterpret_cast<__half2*>(&u.y);
        float2 f0 = __half22float2(h0);
        float2 f1 = __half22float2(h1);
        acc.x += f0.x; acc.y += f0.y; acc.z += f1.x; acc.w += f1.y;
    }
    float di = g_dinv[w];
    float4 bv = ((const float4*)b)[lane];
    float4 r;
    r.x = acc.x * di + bv.x;
    r.y = acc.y * di + bv.y;
    r.z = acc.z * di + bv.z;
    r.w = acc.w * di + bv.w;
    if (doRelu) {
        r.x = fmaxf(r.x, 0.f); r.y = fmaxf(r.y, 0.f);
        r.z = fmaxf(r.z, 0.f); r.w = fmaxf(r.w, 0.f);
    }
    if (outh) {
        uint2 u;
        *reinterpret_cast<__half2*>(&u.x) = __floats2half2_rn(r.x, r.y);
        *reinterpret_cast<__half2*>(&u.y) = __floats2half2_rn(r.z, r.w);
        *(uint2*)&outh[(size_t)w * D + lane * 4] = u;
    } else {
        *(float4*)&outf[(size_t)w * D + lane * 4] = r;
    }
}

// ---------------- attr passthrough / counter cleanup ----------------
__global__ void k_copy_attr(const float4* __restrict__ in, float4* __restrict__ out) {
    int i = blockIdx.x * blockDim.x + threadIdx.x;
    if (i < ATTR_VEC4) out[i] = in[i];
}
__global__ void k_cleanup() {
    int i = blockIdx.x * blockDim.x + threadIdx.x;
    if (i < N_EDGES) { g_cnt_e[i] = 0; g_cur_e[i] = 0; }
    if (i < N_NODES) { g_cnt_n[i] = 0; g_cur_n[i] = 0; }
    if (i < 2) g_cursors[i] = 0;
}

// ---------------- launch (R15 topology + widened xconv on s2) ----------
extern "C" void kernel_launch(void* const* d_in, const int* in_sizes, int n_in,
                              void* d_out, int out_size) {
    const float* x        = (const float*)d_in[0];
    const int*   node_idx = (const int*)  d_in[1];
    const int*   edge_idx = (const int*)  d_in[2];
    const float* attr     = (const float*)d_in[3];
    const float* W1 = (const float*)d_in[4];
    const float* b1 = (const float*)d_in[5];
    const float* W2 = (const float*)d_in[6];
    const float* b2 = (const float*)d_in[7];
    const float* W3 = (const float*)d_in[8];
    const float* b3 = (const float*)d_in[9];
    float* out = (float*)d_out;

    static cudaStream_t s1 = nullptr, s2 = nullptr;
    static cudaEvent_t  e0, e_fe, e_ncsr, e_ws, e_xc, e_j;
    static cudaEvent_t  e_g1[3], e_h[3];
    if (!s1) {
        cudaStreamCreateWithFlags(&s1, cudaStreamNonBlocking);
        cudaStreamCreateWithFlags(&s2, cudaStreamNonBlocking);
        cudaEventCreateWithFlags(&e0,    cudaEventDisableTiming);
        cudaEventCreateWithFlags(&e_fe,  cudaEventDisableTiming);
        cudaEventCreateWithFlags(&e_ncsr,cudaEventDisableTiming);
        cudaEventCreateWithFlags(&e_ws,  cudaEventDisableTiming);
        cudaEventCreateWithFlags(&e_xc,  cudaEventDisableTiming);
        cudaEventCreateWithFlags(&e_j,   cudaEventDisableTiming);
        for (int i = 0; i < 3; i++) {
            cudaEventCreateWithFlags(&e_g1[i], cudaEventDisableTiming);
            cudaEventCreateWithFlags(&e_h[i],  cudaEventDisableTiming);
        }
    }

    float* p_es;
    __half *p_xh, *p_hh;
    cudaGetSymbolAddress((void**)&p_es, g_es);
    cudaGetSymbolAddress((void**)&p_xh, g_xh);
    cudaGetSymbolAddress((void**)&p_hh, g_hh);

    const int half_tiles = E_SPLIT / 128;                       // 98
    const int eg0_grid   = (E_SPLIT * 32) / 256;                // 1568
    const int eg1_grid   = ((N_EDGES - E_SPLIT) * 32 + 255) / 256;
    const int ng_grid    = (N_NODES * 32 + 255) / 256;          // 12500
    const int inc_grid   = (N_INC + 255) / 256;

    cudaEventRecord(e0, 0);

    // s0: edge-side CSR (critical path)
    k_count_e <<<inc_grid, 256>>>(edge_idx);
    k_assign_e<<<(N_EDGES + 255) / 256, 256>>>();
    k_fill_e  <<<inc_grid, 256>>>(node_idx, edge_idx);
    cudaEventRecord(e_fe, 0);

    // s2: widened xconv at head (only needs x); layer half1 work follows
    cudaStreamWaitEvent(s2, e0, 0);
    k_xconv<<<(N_NODES * D / 8 + 255) / 256, 256, 0, s2>>>(x);
    cudaEventRecord(e_xc, s2);

    // s1: wsplit, node CSR, attr, cleanup (overlapped; no xconv prefix)
    cudaStreamWaitEvent(s1, e0, 0);
    k_wsplit  <<<(3 * 16384 + 255) / 256, 256, 0, s1>>>(W1, W2, W3);
    cudaEventRecord(e_ws, s1);
    k_count_n <<<inc_grid, 256, 0, s1>>>(node_idx);
    k_assign_n<<<(N_NODES + 255) / 256, 256, 0, s1>>>();
    k_fill_n  <<<inc_grid, 256, 0, s1>>>(node_idx, edge_idx);
    cudaEventRecord(e_ncsr, s1);
    k_copy_attr<<<(ATTR_VEC4 + 255) / 256, 256, 0, s1>>>(
        (const float4*)attr, (float4*)(out + (size_t)N_NODES * D));
    cudaStreamWaitEvent(s1, e_fe, 0);
    k_cleanup<<<(N_NODES + 255) / 256, 256, 0, s1>>>();
    cudaEventRecord(e_j, s1);

    // layers: s0 does half0 + ng; s2 does half1
    const __half* layer_in[3] = { p_xh, p_hh, p_hh };
    for (int l = 0; l < 3; l++) {
        const float* bb = (l == 0) ? b1 : (l == 1) ? b2 : b3;
        // s2: second half (xconv is same-stream; wait CSR / prev layer)
        cudaStreamWaitEvent(s2, (l == 0) ? e_fe : e_h[l - 1], 0);
        k_edge_gather<<<eg1_grid, 256, 0, s2>>>(layer_in[l], E_SPLIT, N_EDGES);
        if (l == 0) cudaStreamWaitEvent(s2, e_ws, 0);
        k_gemm_mma<<<half_tiles, 256, 0, s2>>>(p_es, l, E_SPLIT, N_EDGES);
        cudaEventRecord(e_g1[l], s2);

        // s0: first half (needs xconv for layer 0)
        if (l == 0) cudaStreamWaitEvent(0, e_xc, 0);
        k_edge_gather<<<eg0_grid, 256>>>(layer_in[l], 0, E_SPLIT);
        if (l == 0) cudaStreamWaitEvent(0, e_ws, 0);
        k_gemm_mma<<<half_tiles, 256>>>(p_es, l, 0, N_EDGES);
        if (l == 0) cudaStreamWaitEvent(0, e_ncsr, 0);
        cudaStreamWaitEvent(0, e_g1[l], 0);
        if (l < 2) k_node_gather<<<ng_grid, 256>>>(nullptr, p_hh, bb, 1);
        else       k_node_gather<<<ng_grid, 256>>>(out, nullptr, bb, 0);
        cudaEventRecord(e_h[l], 0);
    }

    cudaStreamWaitEvent(0, e_j, 0);
}